// round 12
// baseline (speedup 1.0000x reference)
#include <cuda_runtime.h>
#include <cuda_fp16.h>
#include <cstdint>

#define PP 3
#define CC 32
#define HH 256
#define WW 256
#define HW (HH * WW)

// Parity-duplicated, x-pair-interleaved fp16 texture (50.3 MB):
//   g_tex[p][par][y][b][c][e],  b = x-pair block (128/row), e = {west,east}
__device__ __align__(16) __half g_tex[PP * 2 * HH * 128 * CC * 2];
// Folded projection: ix = x*A[0]+y*A[1]+z*A[2]+127.5 ; iy = x*A[3..5]+127.5
__device__ float g_mat[PP * 6];

// ---- cache-policy helpers (createpolicy + cache_hint; width-agnostic) ------
__device__ __forceinline__ uint64_t policy_evict_last() {
    uint64_t p;
    asm("createpolicy.fractional.L2::evict_last.b64 %0, 1.0;" : "=l"(p));
    return p;
}
__device__ __forceinline__ uint4 ldg_el(const uint4* a, uint64_t pol) {
    uint4 v;
    asm volatile("ld.global.nc.L2::cache_hint.v4.u32 {%0,%1,%2,%3}, [%4], %5;"
                 : "=r"(v.x), "=r"(v.y), "=r"(v.z), "=r"(v.w)
                 : "l"(a), "l"(pol));
    return v;
}
__device__ __forceinline__ void stg_el_u4(uint4* a, uint4 v, uint64_t pol) {
    asm volatile("st.global.L2::cache_hint.v4.u32 [%0], {%1,%2,%3,%4}, %5;"
                 :: "l"(a), "r"(v.x), "r"(v.y), "r"(v.z), "r"(v.w), "l"(pol)
                 : "memory");
}

// ---------------------------------------------------------------------------
// Transpose: block = one (plane, y) row; also computes folded matrices.
// Phase 2 packs 4 consecutive channel-half2s into one uint4 store (4x fewer
// store instructions than the scalar version).
// ---------------------------------------------------------------------------
__global__ void __launch_bounds__(256) transpose_kernel(
    const float* __restrict__ in,
    const float* __restrict__ planes,
    const int* __restrict__ bw_raw) {
    if (blockIdx.x == 0 && blockIdx.y == 0 && threadIdx.x == 0) {
        int bits = bw_raw[0];
        float bw;
        if (bits > 0 && bits < 1000000) bw = (float)bits;          // int payload
        else                            bw = __int_as_float(bits); // float payload
        float s = 2.0f / bw;
        float k = s * 0.5f * (WW - 1);

        for (int p = 0; p < PP; p++) {
            const float* a = planes + p * 9;
            float a00=a[0],a01=a[1],a02=a[2];
            float a10=a[3],a11=a[4],a12=a[5];
            float a20=a[6],a21=a[7],a22=a[8];
            float c00 =  (a11*a22 - a12*a21);
            float c01 = -(a10*a22 - a12*a20);
            float c02 =  (a10*a21 - a11*a20);
            float c10 = -(a01*a22 - a02*a21);
            float c11 =  (a00*a22 - a02*a20);
            float c12 = -(a00*a21 - a01*a20);
            float c20 =  (a01*a12 - a02*a11);
            float c21 = -(a00*a12 - a02*a10);
            float c22 =  (a00*a11 - a01*a10);
            float det = a00*c00 + a01*c01 + a02*c02;
            float id  = 1.0f / det;
            float i00=c00*id, i10=c01*id, i20=c02*id;   // inv col 0
            float i01=c10*id, i11=c11*id, i21=c12*id;   // inv col 1
            float* o = g_mat + p * 6;
            o[0]=i00*k; o[1]=i10*k; o[2]=i20*k;
            o[3]=i01*k; o[4]=i11*k; o[5]=i21*k;
        }
    }

    __shared__ float tile[CC][257];
    int y   = blockIdx.x;
    int p   = blockIdx.y;
    int tid = threadIdx.x;

    const float4* in4 = (const float4*)in + (size_t)p * CC * (HW / 4);
    int c = tid >> 3;
    int f = tid & 7;
    #pragma unroll
    for (int r = 0; r < 8; r++) {
        int x4 = f + r * 8;
        float4 v = __ldg(in4 + (size_t)c * (HW / 4) + (size_t)y * 64 + x4);
        tile[c][4*x4 + 0] = v.x;
        tile[c][4*x4 + 1] = v.y;
        tile[c][4*x4 + 2] = v.z;
        tile[c][4*x4 + 3] = v.w;
    }
    __syncthreads();

    // Phase 2: one uint4 = channels 4k..4k+3 (as half2 pairs) of block (par,b)
    uint64_t pol = policy_evict_last();
    uint4* dst = (uint4*)g_tex;        // 8 uint4 per 128B block
    #pragma unroll
    for (int r = 0; r < 8; r++) {
        int idx = r * 256 + tid;       // 0..2047
        int c4  = idx & 7;             // uint4 slot within block
        int b   = (idx >> 3) & 127;
        int par = idx >> 10;
        int xw  = 2*b + par;
        int xe  = min(xw + 1, WW - 1);
        int cb  = c4 * 4;
        __half2 h0 = __floats2half2_rn(tile[cb+0][xw], tile[cb+0][xe]);
        __half2 h1 = __floats2half2_rn(tile[cb+1][xw], tile[cb+1][xe]);
        __half2 h2 = __floats2half2_rn(tile[cb+2][xw], tile[cb+2][xe]);
        __half2 h3 = __floats2half2_rn(tile[cb+3][xw], tile[cb+3][xe]);
        uint4 v = make_uint4(*(unsigned*)&h0, *(unsigned*)&h1,
                             *(unsigned*)&h2, *(unsigned*)&h3);
        stg_el_u4(dst + (size_t)((p*2 + par)*HH + y) * 1024 + b * 8 + c4,
                  v, pol);
    }
}

// ---------------------------------------------------------------------------
// Sampler: two-phase smem-staged (R10 shape: single-round loop, regs ~32,
// occ ~91%). EXACT=true drops all bounds checks (PPM % 256 == 0).
// ---------------------------------------------------------------------------
__device__ __forceinline__ float2 h2f(unsigned u) {
    return __half22float2(*reinterpret_cast<__half2*>(&u));
}

template <bool EXACT>
__global__ void __launch_bounds__(256) sample_kernel(
    const float* __restrict__ coords, float* __restrict__ out, int M) {
    __shared__ float sp[256][8];   // [r0bits, r1bits, c0w, c0e, c1w, c1e, -, -]

    int tid  = threadIdx.x;
    int base = blockIdx.x * 256;
    int PPM  = PP * M;

    // ---- Phase 1: per-point params (1 point per thread) ----
    int pm = base + tid;
    if (EXACT || pm < PPM) {
        int p = (pm >= 2*M) ? 2 : (pm >= M ? 1 : 0);
        int m = pm - p * M;

        const float* cp = coords + 3 * m;
        float x = __ldg(cp), y = __ldg(cp + 1), z = __ldg(cp + 2);

        const float* A = g_mat + p * 6;
        float ix = x*A[0] + y*A[1] + z*A[2] + 0.5f * (WW - 1);
        float iy = x*A[3] + y*A[4] + z*A[5] + 0.5f * (HH - 1);
        float fx = floorf(ix), fy = floorf(iy);

        float wxe = ix - fx;
        float wxw = (fx + 1.0f) - ix;
        float wys = iy - fy;
        float wyn = (fy + 1.0f) - iy;

        int fxi = (int)fx;
        int fyi = (int)fy;
        if (fxi > WW - 2) { wxe = wxw + wxe; wxw = 0.0f; }
        if (fxi < 0)      { wxw = wxw + wxe; wxe = 0.0f; }
        int bx = min(max(fxi, 0), WW - 2);
        int y0 = min(max(fyi,     0), HH - 1);
        int y1 = min(max(fyi + 1, 0), HH - 1);

        int par = bx & 1;
        int xb  = bx >> 1;
        int rowbase = (p*2 + par) * HH;
        int r0 = (rowbase + y0) * 1024 + xb * 8;   // uint4 index of 128B line
        int r1 = (rowbase + y1) * 1024 + xb * 8;

        float4* s = (float4*)sp[tid];
        s[0] = make_float4(__int_as_float(r0), __int_as_float(r1),
                           wyn * wxw, wyn * wxe);
        s[1] = make_float4(wys * wxw, wys * wxe, 0.0f, 0.0f);
    }
    __syncthreads();

    // ---- Phase 2: cooperative gather, 8 lanes per point ----
    const uint4* tex = (const uint4*)g_tex;
    float4* out4 = (float4*)out;
    uint64_t pol = policy_evict_last();
    int q  = tid & 7;
    int jb = tid >> 3;                 // 0..31

    #pragma unroll 2
    for (int r = 0; r < 8; r++) {
        int j   = jb + r * 32;
        int pmj = base + j;
        if (!EXACT && pmj >= PPM) continue;

        float4 pa = ((float4*)sp[j])[0];
        float4 pb = ((float4*)sp[j])[1];
        int r0 = __float_as_int(pa.x) + q;
        int r1 = __float_as_int(pa.y) + q;
        uint4 u0 = ldg_el(tex + r0, pol);
        uint4 u1 = ldg_el(tex + r1, pol);
        float c0w = pa.z, c0e = pa.w, c1w = pb.x, c1e = pb.y;

        float2 f0, f1;
        float4 rr;
        f0 = h2f(u0.x); f1 = h2f(u1.x);
        rr.x = c0w*f0.x + c0e*f0.y + c1w*f1.x + c1e*f1.y;
        f0 = h2f(u0.y); f1 = h2f(u1.y);
        rr.y = c0w*f0.x + c0e*f0.y + c1w*f1.x + c1e*f1.y;
        f0 = h2f(u0.z); f1 = h2f(u1.z);
        rr.z = c0w*f0.x + c0e*f0.y + c1w*f1.x + c1e*f1.y;
        f0 = h2f(u0.w); f1 = h2f(u1.w);
        rr.w = c0w*f0.x + c0e*f0.y + c1w*f1.x + c1e*f1.y;

        __stcs(&out4[pmj * 8 + q], rr);
    }
}

// ---------------------------------------------------------------------------
extern "C" void kernel_launch(void* const* d_in, const int* in_sizes, int n_in,
                              void* d_out, int out_size) {
    const float* feats  = (const float*)d_in[0];   // [1,3,32,256,256] fp32
    const float* coords = (const float*)d_in[1];   // [1,M,3] fp32
    const float* planes = (const float*)d_in[2];   // [3,3,3] fp32
    const int*   bw     = (const int*)d_in[3];     // scalar box_warp

    int M = in_sizes[1] / 3;

    dim3 tg(HH, PP);
    transpose_kernel<<<tg, 256>>>(feats, planes, bw);

    int PPM = PP * M;
    int blocks = (PPM + 255) / 256;
    if (PPM % 256 == 0)
        sample_kernel<true><<<blocks, 256>>>(coords, (float*)d_out, M);
    else
        sample_kernel<false><<<blocks, 256>>>(coords, (float*)d_out, M);
}

// round 13
// speedup vs baseline: 1.0456x; 1.0456x over previous
#include <cuda_runtime.h>
#include <cuda_fp16.h>
#include <cstdint>

#define PP 3
#define CC 32
#define HH 256
#define WW 256
#define HW (HH * WW)

// Parity-duplicated, x-pair-interleaved fp16 texture (50.3 MB):
//   g_tex[p][par][y][b][c][e],  b = x-pair block (128/row), e = {west,east}
__device__ __align__(16) __half g_tex[PP * 2 * HH * 128 * CC * 2];
// Folded projection: ix = x*A[0]+y*A[1]+z*A[2]+127.5 ; iy = x*A[3..5]+127.5
__device__ float g_mat[PP * 6];

// ---- cache-policy helpers ---------------------------------------------------
__device__ __forceinline__ uint64_t policy_evict_last() {
    uint64_t p;
    asm("createpolicy.fractional.L2::evict_last.b64 %0, 1.0;" : "=l"(p));
    return p;
}
// Gather: stream through L1 (no line allocation - zero reuse), pin in L2.
__device__ __forceinline__ uint4 ldg_nal(const uint4* a, uint64_t pol) {
    uint4 v;
    asm volatile(
        "ld.global.L1::no_allocate.L2::cache_hint.v4.u32 {%0,%1,%2,%3}, [%4], %5;"
        : "=r"(v.x), "=r"(v.y), "=r"(v.z), "=r"(v.w)
        : "l"(a), "l"(pol));
    return v;
}
__device__ __forceinline__ void stg_el_u4(uint4* a, uint4 v, uint64_t pol) {
    asm volatile("st.global.L2::cache_hint.v4.u32 [%0], {%1,%2,%3,%4}, %5;"
                 :: "l"(a), "r"(v.x), "r"(v.y), "r"(v.z), "r"(v.w), "l"(pol)
                 : "memory");
}

// ---------------------------------------------------------------------------
// Transpose: block = one (plane, y) row; also computes folded matrices.
// Phase 2 packs 4 consecutive channel-half2s into one uint4 store.
// ---------------------------------------------------------------------------
__global__ void __launch_bounds__(256) transpose_kernel(
    const float* __restrict__ in,
    const float* __restrict__ planes,
    const int* __restrict__ bw_raw) {
    if (blockIdx.x == 0 && blockIdx.y == 0 && threadIdx.x == 0) {
        int bits = bw_raw[0];
        float bw;
        if (bits > 0 && bits < 1000000) bw = (float)bits;          // int payload
        else                            bw = __int_as_float(bits); // float payload
        float s = 2.0f / bw;
        float k = s * 0.5f * (WW - 1);

        for (int p = 0; p < PP; p++) {
            const float* a = planes + p * 9;
            float a00=a[0],a01=a[1],a02=a[2];
            float a10=a[3],a11=a[4],a12=a[5];
            float a20=a[6],a21=a[7],a22=a[8];
            float c00 =  (a11*a22 - a12*a21);
            float c01 = -(a10*a22 - a12*a20);
            float c02 =  (a10*a21 - a11*a20);
            float c10 = -(a01*a22 - a02*a21);
            float c11 =  (a00*a22 - a02*a20);
            float c12 = -(a00*a21 - a01*a20);
            float c20 =  (a01*a12 - a02*a11);
            float c21 = -(a00*a12 - a02*a10);
            float c22 =  (a00*a11 - a01*a10);
            float det = a00*c00 + a01*c01 + a02*c02;
            float id  = 1.0f / det;
            float i00=c00*id, i10=c01*id, i20=c02*id;   // inv col 0
            float i01=c10*id, i11=c11*id, i21=c12*id;   // inv col 1
            float* o = g_mat + p * 6;
            o[0]=i00*k; o[1]=i10*k; o[2]=i20*k;
            o[3]=i01*k; o[4]=i11*k; o[5]=i21*k;
        }
    }

    __shared__ float tile[CC][257];
    int y   = blockIdx.x;
    int p   = blockIdx.y;
    int tid = threadIdx.x;

    const float4* in4 = (const float4*)in + (size_t)p * CC * (HW / 4);
    int c = tid >> 3;
    int f = tid & 7;
    #pragma unroll
    for (int r = 0; r < 8; r++) {
        int x4 = f + r * 8;
        float4 v = __ldg(in4 + (size_t)c * (HW / 4) + (size_t)y * 64 + x4);
        tile[c][4*x4 + 0] = v.x;
        tile[c][4*x4 + 1] = v.y;
        tile[c][4*x4 + 2] = v.z;
        tile[c][4*x4 + 3] = v.w;
    }
    __syncthreads();

    uint64_t pol = policy_evict_last();
    uint4* dst = (uint4*)g_tex;        // 8 uint4 per 128B block
    #pragma unroll
    for (int r = 0; r < 8; r++) {
        int idx = r * 256 + tid;       // 0..2047
        int c4  = idx & 7;             // uint4 slot within block
        int b   = (idx >> 3) & 127;
        int par = idx >> 10;
        int xw  = 2*b + par;
        int xe  = min(xw + 1, WW - 1);
        int cb  = c4 * 4;
        __half2 h0 = __floats2half2_rn(tile[cb+0][xw], tile[cb+0][xe]);
        __half2 h1 = __floats2half2_rn(tile[cb+1][xw], tile[cb+1][xe]);
        __half2 h2 = __floats2half2_rn(tile[cb+2][xw], tile[cb+2][xe]);
        __half2 h3 = __floats2half2_rn(tile[cb+3][xw], tile[cb+3][xe]);
        uint4 v = make_uint4(*(unsigned*)&h0, *(unsigned*)&h1,
                             *(unsigned*)&h2, *(unsigned*)&h3);
        stg_el_u4(dst + (size_t)((p*2 + par)*HH + y) * 1024 + b * 8 + c4,
                  v, pol);
    }
}

// ---------------------------------------------------------------------------
// Sampler: two-phase smem-staged (R10 shape). Gathers bypass L1 allocation.
// ---------------------------------------------------------------------------
__device__ __forceinline__ float2 h2f(unsigned u) {
    return __half22float2(*reinterpret_cast<__half2*>(&u));
}

template <bool EXACT>
__global__ void __launch_bounds__(256) sample_kernel(
    const float* __restrict__ coords, float* __restrict__ out, int M) {
    __shared__ float sp[256][8];   // [r0bits, r1bits, c0w, c0e, c1w, c1e, -, -]

    int tid  = threadIdx.x;
    int base = blockIdx.x * 256;
    int PPM  = PP * M;

    // ---- Phase 1: per-point params (1 point per thread) ----
    int pm = base + tid;
    if (EXACT || pm < PPM) {
        int p = (pm >= 2*M) ? 2 : (pm >= M ? 1 : 0);
        int m = pm - p * M;

        const float* cp = coords + 3 * m;
        float x = __ldg(cp), y = __ldg(cp + 1), z = __ldg(cp + 2);

        const float* A = g_mat + p * 6;
        float ix = x*A[0] + y*A[1] + z*A[2] + 0.5f * (WW - 1);
        float iy = x*A[3] + y*A[4] + z*A[5] + 0.5f * (HH - 1);
        float fx = floorf(ix), fy = floorf(iy);

        float wxe = ix - fx;
        float wxw = (fx + 1.0f) - ix;
        float wys = iy - fy;
        float wyn = (fy + 1.0f) - iy;

        int fxi = (int)fx;
        int fyi = (int)fy;
        if (fxi > WW - 2) { wxe = wxw + wxe; wxw = 0.0f; }
        if (fxi < 0)      { wxw = wxw + wxe; wxe = 0.0f; }
        int bx = min(max(fxi, 0), WW - 2);
        int y0 = min(max(fyi,     0), HH - 1);
        int y1 = min(max(fyi + 1, 0), HH - 1);

        int par = bx & 1;
        int xb  = bx >> 1;
        int rowbase = (p*2 + par) * HH;
        int r0 = (rowbase + y0) * 1024 + xb * 8;   // uint4 index of 128B line
        int r1 = (rowbase + y1) * 1024 + xb * 8;

        float4* s = (float4*)sp[tid];
        s[0] = make_float4(__int_as_float(r0), __int_as_float(r1),
                           wyn * wxw, wyn * wxe);
        s[1] = make_float4(wys * wxw, wys * wxe, 0.0f, 0.0f);
    }
    __syncthreads();

    // ---- Phase 2: cooperative gather, 8 lanes per point ----
    const uint4* tex = (const uint4*)g_tex;
    float4* out4 = (float4*)out;
    uint64_t pol = policy_evict_last();
    int q  = tid & 7;
    int jb = tid >> 3;                 // 0..31

    #pragma unroll 2
    for (int r = 0; r < 8; r++) {
        int j   = jb + r * 32;
        int pmj = base + j;
        if (!EXACT && pmj >= PPM) continue;

        float4 pa = ((float4*)sp[j])[0];
        float4 pb = ((float4*)sp[j])[1];
        int r0 = __float_as_int(pa.x) + q;
        int r1 = __float_as_int(pa.y) + q;
        uint4 u0 = ldg_nal(tex + r0, pol);
        uint4 u1 = ldg_nal(tex + r1, pol);
        float c0w = pa.z, c0e = pa.w, c1w = pb.x, c1e = pb.y;

        float2 f0, f1;
        float4 rr;
        f0 = h2f(u0.x); f1 = h2f(u1.x);
        rr.x = c0w*f0.x + c0e*f0.y + c1w*f1.x + c1e*f1.y;
        f0 = h2f(u0.y); f1 = h2f(u1.y);
        rr.y = c0w*f0.x + c0e*f0.y + c1w*f1.x + c1e*f1.y;
        f0 = h2f(u0.z); f1 = h2f(u1.z);
        rr.z = c0w*f0.x + c0e*f0.y + c1w*f1.x + c1e*f1.y;
        f0 = h2f(u0.w); f1 = h2f(u1.w);
        rr.w = c0w*f0.x + c0e*f0.y + c1w*f1.x + c1e*f1.y;

        __stcs(&out4[pmj * 8 + q], rr);
    }
}

// ---------------------------------------------------------------------------
extern "C" void kernel_launch(void* const* d_in, const int* in_sizes, int n_in,
                              void* d_out, int out_size) {
    const float* feats  = (const float*)d_in[0];   // [1,3,32,256,256] fp32
    const float* coords = (const float*)d_in[1];   // [1,M,3] fp32
    const float* planes = (const float*)d_in[2];   // [3,3,3] fp32
    const int*   bw     = (const int*)d_in[3];     // scalar box_warp

    int M = in_sizes[1] / 3;

    dim3 tg(HH, PP);
    transpose_kernel<<<tg, 256>>>(feats, planes, bw);

    int PPM = PP * M;
    int blocks = (PPM + 255) / 256;
    if (PPM % 256 == 0)
        sample_kernel<true><<<blocks, 256>>>(coords, (float*)d_out, M);
    else
        sample_kernel<false><<<blocks, 256>>>(coords, (float*)d_out, M);
}

// round 14
// speedup vs baseline: 1.0868x; 1.0394x over previous
#include <cuda_runtime.h>
#include <cuda_fp16.h>
#include <cstdint>

#define PP 3
#define CC 32
#define HH 256
#define WW 256
#define HW (HH * WW)

// Parity-duplicated, x-pair-interleaved fp16 texture (50.3 MB):
//   g_tex[p][par][y][b][c][e],  b = x-pair block (128/row), e = {west,east}
__device__ __align__(16) __half g_tex[PP * 2 * HH * 128 * CC * 2];
// Folded projection: ix = x*A[0]+y*A[1]+z*A[2]+127.5 ; iy = x*A[3..5]+127.5
__device__ float g_mat[PP * 6];

// ---- cache-policy helpers ---------------------------------------------------
__device__ __forceinline__ uint64_t policy_evict_last() {
    uint64_t p;
    asm("createpolicy.fractional.L2::evict_last.b64 %0, 1.0;" : "=l"(p));
    return p;
}
// Gather: stream through L1 (no allocation - zero reuse), pin in L2.
__device__ __forceinline__ uint4 ldg_nal(const uint4* a, uint64_t pol) {
    uint4 v;
    asm volatile(
        "ld.global.L1::no_allocate.L2::cache_hint.v4.u32 {%0,%1,%2,%3}, [%4], %5;"
        : "=r"(v.x), "=r"(v.y), "=r"(v.z), "=r"(v.w)
        : "l"(a), "l"(pol));
    return v;
}
__device__ __forceinline__ void stg_el_u4(uint4* a, uint4 v, uint64_t pol) {
    asm volatile("st.global.L2::cache_hint.v4.u32 [%0], {%1,%2,%3,%4}, %5;"
                 :: "l"(a), "r"(v.x), "r"(v.y), "r"(v.z), "r"(v.w), "l"(pol)
                 : "memory");
}

// ---------------------------------------------------------------------------
// Transpose: block = one (plane, y) row; also computes folded matrices.
// ---------------------------------------------------------------------------
__global__ void __launch_bounds__(256) transpose_kernel(
    const float* __restrict__ in,
    const float* __restrict__ planes,
    const int* __restrict__ bw_raw) {
    if (blockIdx.x == 0 && blockIdx.y == 0 && threadIdx.x == 0) {
        int bits = bw_raw[0];
        float bw;
        if (bits > 0 && bits < 1000000) bw = (float)bits;          // int payload
        else                            bw = __int_as_float(bits); // float payload
        float s = 2.0f / bw;
        float k = s * 0.5f * (WW - 1);

        for (int p = 0; p < PP; p++) {
            const float* a = planes + p * 9;
            float a00=a[0],a01=a[1],a02=a[2];
            float a10=a[3],a11=a[4],a12=a[5];
            float a20=a[6],a21=a[7],a22=a[8];
            float c00 =  (a11*a22 - a12*a21);
            float c01 = -(a10*a22 - a12*a20);
            float c02 =  (a10*a21 - a11*a20);
            float c10 = -(a01*a22 - a02*a21);
            float c11 =  (a00*a22 - a02*a20);
            float c12 = -(a00*a21 - a01*a20);
            float c20 =  (a01*a12 - a02*a11);
            float c21 = -(a00*a12 - a02*a10);
            float c22 =  (a00*a11 - a01*a10);
            float det = a00*c00 + a01*c01 + a02*c02;
            float id  = 1.0f / det;
            float i00=c00*id, i10=c01*id, i20=c02*id;   // inv col 0
            float i01=c10*id, i11=c11*id, i21=c12*id;   // inv col 1
            float* o = g_mat + p * 6;
            o[0]=i00*k; o[1]=i10*k; o[2]=i20*k;
            o[3]=i01*k; o[4]=i11*k; o[5]=i21*k;
        }
    }

    __shared__ float tile[CC][257];
    int y   = blockIdx.x;
    int p   = blockIdx.y;
    int tid = threadIdx.x;

    const float4* in4 = (const float4*)in + (size_t)p * CC * (HW / 4);
    int c = tid >> 3;
    int f = tid & 7;
    #pragma unroll
    for (int r = 0; r < 8; r++) {
        int x4 = f + r * 8;
        float4 v = __ldg(in4 + (size_t)c * (HW / 4) + (size_t)y * 64 + x4);
        tile[c][4*x4 + 0] = v.x;
        tile[c][4*x4 + 1] = v.y;
        tile[c][4*x4 + 2] = v.z;
        tile[c][4*x4 + 3] = v.w;
    }
    __syncthreads();

    uint64_t pol = policy_evict_last();
    uint4* dst = (uint4*)g_tex;        // 8 uint4 per 128B block
    #pragma unroll
    for (int r = 0; r < 8; r++) {
        int idx = r * 256 + tid;       // 0..2047
        int c4  = idx & 7;             // uint4 slot within block
        int b   = (idx >> 3) & 127;
        int par = idx >> 10;
        int xw  = 2*b + par;
        int xe  = min(xw + 1, WW - 1);
        int cb  = c4 * 4;
        __half2 h0 = __floats2half2_rn(tile[cb+0][xw], tile[cb+0][xe]);
        __half2 h1 = __floats2half2_rn(tile[cb+1][xw], tile[cb+1][xe]);
        __half2 h2 = __floats2half2_rn(tile[cb+2][xw], tile[cb+2][xe]);
        __half2 h3 = __floats2half2_rn(tile[cb+3][xw], tile[cb+3][xe]);
        uint4 v = make_uint4(*(unsigned*)&h0, *(unsigned*)&h1,
                             *(unsigned*)&h2, *(unsigned*)&h3);
        stg_el_u4(dst + (size_t)((p*2 + par)*HH + y) * 1024 + b * 8 + c4,
                  v, pol);
    }
}

// ---------------------------------------------------------------------------
// Sampler: two-phase smem-staged; params compressed to ONE float4 per point
// {r0, r1, wxw, wys} (wxe = 1-wxw and wyn = 1-wys are exact after folding).
// Phase 2 octets reconstruct corner weights in-lane.
// ---------------------------------------------------------------------------
__device__ __forceinline__ float2 h2f(unsigned u) {
    return __half22float2(*reinterpret_cast<__half2*>(&u));
}

template <bool EXACT>
__global__ void __launch_bounds__(256) sample_kernel(
    const float* __restrict__ coords, float* __restrict__ out, int M) {
    __shared__ float4 sp[256];     // {r0bits, r1bits, wxw, wys}

    int tid  = threadIdx.x;
    int base = blockIdx.x * 256;
    int PPM  = PP * M;

    // ---- Phase 1: per-point params (1 point per thread) ----
    int pm = base + tid;
    if (EXACT || pm < PPM) {
        int p = (pm >= 2*M) ? 2 : (pm >= M ? 1 : 0);
        int m = pm - p * M;

        const float* cp = coords + 3 * m;
        float x = __ldg(cp), y = __ldg(cp + 1), z = __ldg(cp + 2);

        const float* A = g_mat + p * 6;
        float ix = x*A[0] + y*A[1] + z*A[2] + 0.5f * (WW - 1);
        float iy = x*A[3] + y*A[4] + z*A[5] + 0.5f * (HH - 1);
        float fx = floorf(ix), fy = floorf(iy);

        float wxe = ix - fx;
        float wxw = (fx + 1.0f) - ix;
        float wys = iy - fy;

        int fxi = (int)fx;
        int fyi = (int)fy;
        // x clamp folded onto the stored in-bounds pair (keeps wxw+wxe == 1)
        if (fxi > WW - 2) { wxw = 0.0f; }
        if (fxi < 0)      { wxw = 1.0f; }
        int bx = min(max(fxi, 0), WW - 2);
        int y0 = min(max(fyi,     0), HH - 1);
        int y1 = min(max(fyi + 1, 0), HH - 1);

        int par = bx & 1;
        int xb  = bx >> 1;
        int rowbase = (p*2 + par) * HH;
        int r0 = (rowbase + y0) * 1024 + xb * 8;   // uint4 index of 128B line
        int r1 = (rowbase + y1) * 1024 + xb * 8;

        sp[tid] = make_float4(__int_as_float(r0), __int_as_float(r1),
                              wxw, wys);
    }
    __syncthreads();

    // ---- Phase 2: cooperative gather, 8 lanes per point ----
    const uint4* tex = (const uint4*)g_tex;
    float4* out4 = (float4*)out;
    uint64_t pol = policy_evict_last();
    int q  = tid & 7;
    int jb = tid >> 3;                 // 0..31

    #pragma unroll 2
    for (int r = 0; r < 8; r++) {
        int j   = jb + r * 32;
        int pmj = base + j;
        if (!EXACT && pmj >= PPM) continue;

        float4 pa = sp[j];
        int r0 = __float_as_int(pa.x) + q;
        int r1 = __float_as_int(pa.y) + q;
        uint4 u0 = ldg_nal(tex + r0, pol);
        uint4 u1 = ldg_nal(tex + r1, pol);

        float wxw = pa.z, wys = pa.w;
        float wxe = 1.0f - wxw;
        float wyn = 1.0f - wys;
        float c0w = wyn * wxw, c0e = wyn * wxe;
        float c1w = wys * wxw, c1e = wys * wxe;

        float2 f0, f1;
        float4 rr;
        f0 = h2f(u0.x); f1 = h2f(u1.x);
        rr.x = c0w*f0.x + c0e*f0.y + c1w*f1.x + c1e*f1.y;
        f0 = h2f(u0.y); f1 = h2f(u1.y);
        rr.y = c0w*f0.x + c0e*f0.y + c1w*f1.x + c1e*f1.y;
        f0 = h2f(u0.z); f1 = h2f(u1.z);
        rr.z = c0w*f0.x + c0e*f0.y + c1w*f1.x + c1e*f1.y;
        f0 = h2f(u0.w); f1 = h2f(u1.w);
        rr.w = c0w*f0.x + c0e*f0.y + c1w*f1.x + c1e*f1.y;

        __stcs(&out4[pmj * 8 + q], rr);
    }
}

// ---------------------------------------------------------------------------
extern "C" void kernel_launch(void* const* d_in, const int* in_sizes, int n_in,
                              void* d_out, int out_size) {
    const float* feats  = (const float*)d_in[0];   // [1,3,32,256,256] fp32
    const float* coords = (const float*)d_in[1];   // [1,M,3] fp32
    const float* planes = (const float*)d_in[2];   // [3,3,3] fp32
    const int*   bw     = (const int*)d_in[3];     // scalar box_warp

    int M = in_sizes[1] / 3;

    dim3 tg(HH, PP);
    transpose_kernel<<<tg, 256>>>(feats, planes, bw);

    int PPM = PP * M;
    int blocks = (PPM + 255) / 256;
    if (PPM % 256 == 0)
        sample_kernel<true><<<blocks, 256>>>(coords, (float*)d_out, M);
    else
        sample_kernel<false><<<blocks, 256>>>(coords, (float*)d_out, M);
}